// round 14
// baseline (speedup 1.0000x reference)
#include <cuda_runtime.h>
#include <math.h>
#include <stdint.h>

// Problem constants
#define BB   8
#define CC   256
#define LL   1024          // H*W
#define DIN  512           // d_inner
#define DST  16            // d_state
#define RANK 16
#define HID  1024
#define MM   (BB*LL)       // 8192 tokens
#define DBLS 128           // padded dbl row stride

// ---------------- scratch (device globals; no allocation APIs) -------------
__device__ float g_xt [MM*CC];     // x transposed (B,L,C) == residual 1
__device__ float g_xn [MM*CC];     // LN1 out
__device__ float g_xz [MM*2*DIN];  // xn @ W_in
__device__ float g_xm [MM*DIN];    // conv+silu out
__device__ float g_dbl[MM*DBLS];   // xm @ W_x padded (dt_raw | B | C | 0..)
__device__ float g_wxp[DIN*DBLS];  // W_x zero-padded to 512x128
__device__ float g_dt [MM*DIN];    // softplus(dt_raw @ W_dt + b_dt)
__device__ float g_yg [MM*DIN];    // gated scan output
__device__ float g_x2 [MM*CC];     // mamba out + res (residual 2)
__device__ float g_xn2[MM*CC];     // LN2 out
__device__ float g_h1 [MM*HID];    // gelu(xn2@W1+b1)
__device__ float g_x3 [MM*CC];     // final (B,L,C) before transpose

// ---------------- batched 2D transpose: (b,R,C) -> (b,C,R) -----------------
__global__ void transpose_k(const float* __restrict__ in, float* __restrict__ out,
                            int R, int Cc) {
    __shared__ float t[32][33];
    int b  = blockIdx.z;
    int r0 = blockIdx.y * 32, c0 = blockIdx.x * 32;
    const float* ib = in  + (size_t)b * R * Cc;
    float*       ob = out + (size_t)b * R * Cc;
#pragma unroll
    for (int i = 0; i < 32; i += 8)
        t[threadIdx.y + i][threadIdx.x] = ib[(r0 + threadIdx.y + i) * Cc + c0 + threadIdx.x];
    __syncthreads();
#pragma unroll
    for (int i = 0; i < 32; i += 8)
        ob[(c0 + threadIdx.y + i) * R + r0 + threadIdx.x] = t[threadIdx.x][threadIdx.y + i];
}

// -------- fused transpose (B,C,L)->(B,L,C) + LayerNorm over C --------------
__global__ __launch_bounds__(256)
void trln_k(const float* __restrict__ in, float* __restrict__ xt,
            float* __restrict__ xn, const float* __restrict__ g,
            const float* __restrict__ bt) {
    __shared__ float t[CC][33];
    __shared__ float ps[8][32], psq[8][32];
    __shared__ float mu[32], rs[32];
    int tx = threadIdx.x, ty = threadIdx.y;   // (32, 8)
    int l0 = blockIdx.x * 32;
    int b  = blockIdx.y;
    const float* ib = in + (size_t)b * CC * LL;

#pragma unroll
    for (int c = ty; c < CC; c += 8)
        t[c][tx] = ib[(size_t)c * LL + l0 + tx];
    __syncthreads();

    float s = 0.f, sq = 0.f;
#pragma unroll
    for (int i = 0; i < 32; i++) {
        float v = t[ty * 32 + i][tx];
        s += v; sq = fmaf(v, v, sq);
    }
    ps[ty][tx] = s; psq[ty][tx] = sq;
    __syncthreads();
    if (ty == 0) {
        float tot = 0.f, totq = 0.f;
#pragma unroll
        for (int i = 0; i < 8; i++) { tot += ps[i][tx]; totq += psq[i][tx]; }
        float m = tot * (1.0f / CC);
        float var = totq * (1.0f / CC) - m * m;
        mu[tx] = m; rs[tx] = rsqrtf(var + 1e-5f);
    }
    __syncthreads();

#pragma unroll
    for (int jj = ty; jj < 32; jj += 8) {
        float m = mu[jj], r = rs[jj];
        size_t base = ((size_t)b * LL + l0 + jj) * CC;
#pragma unroll
        for (int cc = tx; cc < CC; cc += 32) {
            float v = t[cc][jj];
            xt[base + cc] = v;
            xn[base + cc] = (v - m) * r * g[cc] + bt[cc];
        }
    }
}

// ---------------- layernorm over C=256, one block per token (LN2) ----------
__global__ void layernorm_k(const float* __restrict__ in, float* __restrict__ out,
                            const float* __restrict__ g, const float* __restrict__ bt) {
    int row = blockIdx.x;
    int tid = threadIdx.x;          // 256
    float v = in[row * CC + tid];
    float s = v, sq = v * v;
#pragma unroll
    for (int o = 16; o; o >>= 1) {
        s  += __shfl_xor_sync(0xffffffffu, s,  o);
        sq += __shfl_xor_sync(0xffffffffu, sq, o);
    }
    __shared__ float ss[8], ssq[8];
    int w = tid >> 5;
    if ((tid & 31) == 0) { ss[w] = s; ssq[w] = sq; }
    __syncthreads();
    float tot = 0.f, totq = 0.f;
#pragma unroll
    for (int i = 0; i < 8; i++) { tot += ss[i]; totq += ssq[i]; }
    float mu  = tot * (1.0f / CC);
    float var = totq * (1.0f / CC) - mu * mu;
    out[row * CC + tid] = (v - mu) * rsqrtf(var + 1e-5f) * g[tid] + bt[tid];
}

// ---------------- bf16 tensor-core GEMM, double-buffered BK=16 -------------
__device__ __forceinline__ uint32_t pkbf16(float lo, float hi) {
    uint32_t r;
    asm("cvt.rn.bf16x2.f32 %0, %1, %2;" : "=r"(r) : "f"(hi), "f"(lo));
    return r;
}

__device__ __forceinline__ void mma_bf16(float* c, const uint32_t* a,
                                         uint32_t b0, uint32_t b1) {
    asm volatile(
        "mma.sync.aligned.m16n8k16.row.col.f32.bf16.bf16.f32 "
        "{%0,%1,%2,%3}, {%4,%5,%6,%7}, {%8,%9}, {%0,%1,%2,%3};"
        : "+f"(c[0]), "+f"(c[1]), "+f"(c[2]), "+f"(c[3])
        : "r"(a[0]), "r"(a[1]), "r"(a[2]), "r"(a[3]), "r"(b0), "r"(b1));
}

template<int EPI>
__global__ __launch_bounds__(256, 2)
void bf16gemm_k(const float* __restrict__ A, const float* __restrict__ Bm,
                float* __restrict__ Cout, int M, int N, int K,
                const float* __restrict__ bias, const float* __restrict__ res) {
    __shared__ uint32_t As[2][8][132];   // [stage][k2][m]: bf16x2 packs (2k2, 2k2+1)
    __shared__ uint32_t Bs[2][8][132];   // [stage][k2][n]
    int tid  = threadIdx.x;
    int lane = tid & 31, warp = tid >> 5;
    int warpM = warp >> 1, warpN = warp & 1;     // 4 x 2 warps
    int bm = blockIdx.y * 128, bn = blockIdx.x * 128;
    int row4 = lane >> 2, kq = lane & 3;

    float acc[2][8][4];
#pragma unroll
    for (int i = 0; i < 2; i++)
#pragma unroll
        for (int j = 0; j < 8; j++)
#pragma unroll
            for (int q = 0; q < 4; q++) acc[i][j][q] = 0.f;

    // A: each thread owns one row (ar), 8 consecutive k (ac..ac+7)
    int ar = tid >> 1;               // 0..127
    int ac = (tid & 1) << 3;         // 0 or 8
    const float* Ap = A + (size_t)(bm + ar) * K + ac;
    // B: each thread owns k-row pair (2*bk2, 2*bk2+1), 4 consecutive n
    int bk2 = tid >> 5;              // 0..7
    int bn4 = (tid & 31) << 2;       // 0..124
    const float* Bp0 = Bm + (size_t)(2 * bk2) * N + bn + bn4;
    const float* Bp1 = Bp0 + N;

    float4 a0, a1, b0, b1;
    a0 = *(const float4*)(Ap);
    a1 = *(const float4*)(Ap + 4);
    b0 = *(const float4*)(Bp0);
    b1 = *(const float4*)(Bp1);

    // store stage 0
    {
        int k2b = ac >> 1;
        As[0][k2b + 0][ar] = pkbf16(a0.x, a0.y);
        As[0][k2b + 1][ar] = pkbf16(a0.z, a0.w);
        As[0][k2b + 2][ar] = pkbf16(a1.x, a1.y);
        As[0][k2b + 3][ar] = pkbf16(a1.z, a1.w);
        Bs[0][bk2][bn4 + 0] = pkbf16(b0.x, b1.x);
        Bs[0][bk2][bn4 + 1] = pkbf16(b0.y, b1.y);
        Bs[0][bk2][bn4 + 2] = pkbf16(b0.z, b1.z);
        Bs[0][bk2][bn4 + 3] = pkbf16(b0.w, b1.w);
    }
    __syncthreads();

    int nK = K >> 4;
    for (int it = 0; it < nK; it++) {
        int st = it & 1;
        bool more = (it + 1 < nK);
        if (more) {
            int k0 = (it + 1) << 4;
            a0 = *(const float4*)(Ap + k0);
            a1 = *(const float4*)(Ap + k0 + 4);
            b0 = *(const float4*)(Bp0 + (size_t)k0 * N);
            b1 = *(const float4*)(Bp1 + (size_t)k0 * N);
        }
        // compute stage st (one k16 step: k2 = kq and 4+kq)
        {
            uint32_t af[2][4];
#pragma unroll
            for (int mi = 0; mi < 2; mi++) {
                int m0 = warpM * 32 + mi * 16;
                af[mi][0] = As[st][kq][m0 + row4];
                af[mi][1] = As[st][kq][m0 + 8 + row4];
                af[mi][2] = As[st][4 + kq][m0 + row4];
                af[mi][3] = As[st][4 + kq][m0 + 8 + row4];
            }
#pragma unroll
            for (int ni = 0; ni < 8; ni++) {
                int n0 = warpN * 64 + ni * 8;
                uint32_t bb0 = Bs[st][kq][n0 + row4];
                uint32_t bb1 = Bs[st][4 + kq][n0 + row4];
                mma_bf16(acc[0][ni], af[0], bb0, bb1);
                mma_bf16(acc[1][ni], af[1], bb0, bb1);
            }
        }
        if (more) {
            int so = st ^ 1;
            int k2b = ac >> 1;
            As[so][k2b + 0][ar] = pkbf16(a0.x, a0.y);
            As[so][k2b + 1][ar] = pkbf16(a0.z, a0.w);
            As[so][k2b + 2][ar] = pkbf16(a1.x, a1.y);
            As[so][k2b + 3][ar] = pkbf16(a1.z, a1.w);
            Bs[so][bk2][bn4 + 0] = pkbf16(b0.x, b1.x);
            Bs[so][bk2][bn4 + 1] = pkbf16(b0.y, b1.y);
            Bs[so][bk2][bn4 + 2] = pkbf16(b0.z, b1.z);
            Bs[so][bk2][bn4 + 3] = pkbf16(b0.w, b1.w);
        }
        __syncthreads();
    }

    // epilogue
#pragma unroll
    for (int mi = 0; mi < 2; mi++) {
        int r0 = bm + warpM * 32 + mi * 16 + row4;
#pragma unroll
        for (int ni = 0; ni < 8; ni++) {
            int col = bn + warpN * 64 + ni * 8 + kq * 2;
#pragma unroll
            for (int half = 0; half < 2; half++) {
                int row = r0 + half * 8;
                float v0 = acc[mi][ni][half * 2 + 0];
                float v1 = acc[mi][ni][half * 2 + 1];
                if (EPI == 1) {
                    v0 += res[(size_t)row * N + col];
                    v1 += res[(size_t)row * N + col + 1];
                }
                if (EPI == 2) {
                    v0 += bias[col];
                    v1 += bias[col + 1];
                    v0 = 0.5f * v0 * (1.0f + erff(v0 * 0.70710678118654752f));
                    v1 = 0.5f * v1 * (1.0f + erff(v1 * 0.70710678118654752f));
                }
                if (EPI == 3) {
                    v0 += bias[col]     + res[(size_t)row * N + col];
                    v1 += bias[col + 1] + res[(size_t)row * N + col + 1];
                }
                float2 o = make_float2(v0, v1);
                *(float2*)(Cout + (size_t)row * N + col) = o;
            }
        }
    }
}

// ---------------- pad W_x (512x48) -> (512x128, zero-filled) ---------------
__global__ void pad_wx_k(const float* __restrict__ Wx, float* __restrict__ Wxp) {
    int idx = blockIdx.x * blockDim.x + threadIdx.x;   // DIN*DBLS
    int k = idx >> 7, n = idx & 127;
    Wxp[idx] = (n < 48) ? Wx[k * 48 + n] : 0.0f;
}

// ---------------- depthwise causal conv1d (d_conv=4) + silu, float4 --------
__global__ void conv_silu_k(const float* __restrict__ xz, const float* __restrict__ cw,
                            const float* __restrict__ cb, float* __restrict__ xm) {
    int idx = blockIdx.x * blockDim.x + threadIdx.x;   // MM*DIN/4 threads
    if (idx >= MM * DIN / 4) return;
    int d4 = (idx & 127) << 2;       // channel group base (0..508)
    int t  = idx >> 7;               // token index b*L + l
    int l  = t & (LL - 1);
    int b  = t >> 10;
    float4 acc = *(const float4*)(cb + d4);
    float4 w0 = *(const float4*)(cw + (d4 + 0) * 4);
    float4 w1 = *(const float4*)(cw + (d4 + 1) * 4);
    float4 w2 = *(const float4*)(cw + (d4 + 2) * 4);
    float4 w3 = *(const float4*)(cw + (d4 + 3) * 4);
    const float* wx[4] = {&w0.x, &w1.x, &w2.x, &w3.x};
#pragma unroll
    for (int k = 0; k < 4; k++) {
        int ls = l + k - 3;
        if (ls >= 0) {
            float4 v = *(const float4*)(xz + ((size_t)((b << 10) + ls)) * (2 * DIN) + d4);
            acc.x = fmaf(v.x, wx[0][k], acc.x);
            acc.y = fmaf(v.y, wx[1][k], acc.y);
            acc.z = fmaf(v.z, wx[2][k], acc.z);
            acc.w = fmaf(v.w, wx[3][k], acc.w);
        }
    }
    acc.x = acc.x / (1.0f + __expf(-acc.x));
    acc.y = acc.y / (1.0f + __expf(-acc.y));
    acc.z = acc.z / (1.0f + __expf(-acc.z));
    acc.w = acc.w / (1.0f + __expf(-acc.w));
    *(float4*)(xm + (size_t)t * DIN + d4) = acc;
}

// -------- dt = softplus(dbl[:, :16] @ W_dt + b_dt), W in registers ---------
__global__ __launch_bounds__(256)
void dt2_k(const float* __restrict__ dbl, const float* __restrict__ Wdt,
           const float* __restrict__ bdt, float* __restrict__ dt) {
    __shared__ float sdt[32][17];
    int m0 = blockIdx.x * 32;
    int tid = threadIdx.x;
#pragma unroll
    for (int q = 0; q < 2; q++) {
        int e = tid + q * 256;
        sdt[e >> 4][e & 15] = dbl[(size_t)(m0 + (e >> 4)) * DBLS + (e & 15)];
    }
    int c0 = tid, c1 = tid + 256;
    float w0[16], w1[16];
#pragma unroll
    for (int k = 0; k < 16; k++) {
        w0[k] = Wdt[k * DIN + c0];
        w1[k] = Wdt[k * DIN + c1];
    }
    float b0v = bdt[c0], b1v = bdt[c1];
    __syncthreads();
#pragma unroll 4
    for (int r = 0; r < 32; r++) {
        float a0 = b0v, a1 = b1v;
#pragma unroll
        for (int k = 0; k < 16; k++) {
            float av = sdt[r][k];
            a0 = fmaf(av, w0[k], a0);
            a1 = fmaf(av, w1[k], a1);
        }
        a0 = (a0 > 20.f) ? a0 : log1pf(__expf(a0));
        a1 = (a1 > 20.f) ? a1 : log1pf(__expf(a1));
        dt[(size_t)(m0 + r) * DIN + c0] = a0;
        dt[(size_t)(m0 + r) * DIN + c1] = a1;
    }
}

// ------ selective scan v2 + chunk-level gate (NOT per-iteration) -----------
__global__ __launch_bounds__(256)
void scan2_k(const float* __restrict__ dt, const float* __restrict__ xm,
             const float* __restrict__ dbl, const float* __restrict__ Alog,
             const float* __restrict__ xz, const float* __restrict__ Dp,
             float* __restrict__ yg) {
    __shared__ float sdt[2][64][16], sxm[2][64][16];
    __shared__ float sB[2][64][16], sC[2][64][16];
    __shared__ float sz[2][64][16];
    __shared__ float sy[64][16];

    int tid  = threadIdx.x;
    int warp = tid >> 5, lane = tid & 31;
    int ch   = lane >> 4, s = lane & 15;
    int wch  = warp * 2 + ch;            // local channel 0..15
    int b    = blockIdx.y;
    int d0   = blockIdx.x * 16;
    int d    = d0 + wch;
    int tb   = b << 10;

    float a = -__expf(Alog[d * DST + s]);
    float h = 0.f;

    int j4 = tid >> 2;                   // token within chunk 0..63
    int i4 = (tid & 3) << 2;             // float4 offset 0,4,8,12
    float4 Dv = *(const float4*)(Dp + d0 + i4);

    {
        size_t t = (size_t)(tb + j4);
        *(float4*)&sdt[0][j4][i4] = *(const float4*)(dt  + t * DIN + d0 + i4);
        *(float4*)&sxm[0][j4][i4] = *(const float4*)(xm  + t * DIN + d0 + i4);
        *(float4*)&sB [0][j4][i4] = *(const float4*)(dbl + t * DBLS + 16 + i4);
        *(float4*)&sC [0][j4][i4] = *(const float4*)(dbl + t * DBLS + 32 + i4);
        *(float4*)&sz [0][j4][i4] = *(const float4*)(xz  + t * (2 * DIN) + DIN + d0 + i4);
    }
    __syncthreads();

    for (int c = 0; c < LL / 64; c++) {
        float4 rd, rx, rb, rc, rz;
        bool more = (c + 1 < LL / 64);
        if (more) {
            size_t t = (size_t)(tb + (c + 1) * 64 + j4);
            rd = *(const float4*)(dt  + t * DIN + d0 + i4);
            rx = *(const float4*)(xm  + t * DIN + d0 + i4);
            rb = *(const float4*)(dbl + t * DBLS + 16 + i4);
            rc = *(const float4*)(dbl + t * DBLS + 32 + i4);
            rz = *(const float4*)(xz  + t * (2 * DIN) + DIN + d0 + i4);
        }
        int buf = c & 1;
#pragma unroll 4
        for (int j = 0; j < 64; j++) {
            float dtv = sdt[buf][j][wch];
            float xv  = sxm[buf][j][wch];
            float Bv  = sB[buf][j][s];
            float Cv  = sC[buf][j][s];
            float dA  = __expf(dtv * a);
            h = fmaf(dA, h, dtv * xv * Bv);
            float p = h * Cv;
            p += __shfl_xor_sync(0xffffffffu, p, 8);
            p += __shfl_xor_sync(0xffffffffu, p, 4);
            p += __shfl_xor_sync(0xffffffffu, p, 2);
            p += __shfl_xor_sync(0xffffffffu, p, 1);
            if (s == 0) sy[j][wch] = p;
        }
        __syncthreads();
        {
            float4 pv = *(float4*)&sy[j4][i4];
            float4 xv = *(float4*)&sxm[buf][j4][i4];
            float4 zv = *(float4*)&sz[buf][j4][i4];
            float4 o;
            o.x = fmaf(xv.x, Dv.x, pv.x) * (zv.x / (1.0f + __expf(-zv.x)));
            o.y = fmaf(xv.y, Dv.y, pv.y) * (zv.y / (1.0f + __expf(-zv.y)));
            o.z = fmaf(xv.z, Dv.z, pv.z) * (zv.z / (1.0f + __expf(-zv.z)));
            o.w = fmaf(xv.w, Dv.w, pv.w) * (zv.w / (1.0f + __expf(-zv.w)));
            size_t t = (size_t)(tb + c * 64 + j4);
            *(float4*)(yg + t * DIN + d0 + i4) = o;
        }
        if (more) {
            int nb = buf ^ 1;
            *(float4*)&sdt[nb][j4][i4] = rd;
            *(float4*)&sxm[nb][j4][i4] = rx;
            *(float4*)&sB [nb][j4][i4] = rb;
            *(float4*)&sC [nb][j4][i4] = rc;
            *(float4*)&sz [nb][j4][i4] = rz;
        }
        __syncthreads();
    }
}

// ---------------------------- launch ---------------------------------------
extern "C" void kernel_launch(void* const* d_in, const int* in_sizes, int n_in,
                              void* d_out, int out_size) {
    const float* x      = (const float*)d_in[0];
    const float* ln1_g  = (const float*)d_in[1];
    const float* ln1_b  = (const float*)d_in[2];
    const float* ln2_g  = (const float*)d_in[3];
    const float* ln2_b  = (const float*)d_in[4];
    const float* W_in   = (const float*)d_in[5];
    const float* conv_w = (const float*)d_in[6];
    const float* conv_b = (const float*)d_in[7];
    const float* W_x    = (const float*)d_in[8];
    const float* W_dt   = (const float*)d_in[9];
    const float* b_dt   = (const float*)d_in[10];
    const float* A_log  = (const float*)d_in[11];
    const float* D_par  = (const float*)d_in[12];
    const float* W_out  = (const float*)d_in[13];
    const float* W1     = (const float*)d_in[14];
    const float* b1     = (const float*)d_in[15];
    const float* W2     = (const float*)d_in[16];
    const float* b2     = (const float*)d_in[17];
    float* out = (float*)d_out;

    float *xt, *xn, *xz, *xm, *dbl, *wxp, *dtp, *yg, *x2, *xn2, *h1, *x3;
    cudaGetSymbolAddress((void**)&xt,  g_xt);
    cudaGetSymbolAddress((void**)&xn,  g_xn);
    cudaGetSymbolAddress((void**)&xz,  g_xz);
    cudaGetSymbolAddress((void**)&xm,  g_xm);
    cudaGetSymbolAddress((void**)&dbl, g_dbl);
    cudaGetSymbolAddress((void**)&wxp, g_wxp);
    cudaGetSymbolAddress((void**)&dtp, g_dt);
    cudaGetSymbolAddress((void**)&yg,  g_yg);
    cudaGetSymbolAddress((void**)&x2,  g_x2);
    cudaGetSymbolAddress((void**)&xn2, g_xn2);
    cudaGetSymbolAddress((void**)&h1,  g_h1);
    cudaGetSymbolAddress((void**)&x3,  g_x3);

    // 1) fused transpose + LN1
    trln_k<<<dim3(LL / 32, BB), dim3(32, 8)>>>(x, xt, xn, ln1_g, ln1_b);
    // 2) xz = xn @ W_in  (bf16, double-buffered)
    bf16gemm_k<0><<<dim3((2 * DIN) / 128, MM / 128), 256>>>(xn, W_in, xz, MM, 2 * DIN, CC, nullptr, nullptr);
    // 3) depthwise causal conv + silu
    conv_silu_k<<<(MM * DIN / 4) / 256, 256>>>(xz, conv_w, conv_b, xm);
    // 4) pad W_x, then dbl = xm @ W_x (padded)
    pad_wx_k<<<(DIN * DBLS) / 256, 256>>>(W_x, wxp);
    bf16gemm_k<0><<<dim3(DBLS / 128, MM / 128), 256>>>(xm, wxp, dbl, MM, DBLS, DIN, nullptr, nullptr);
    // 5) dt = softplus(dbl[:, :16] @ W_dt + b_dt)
    dt2_k<<<MM / 32, 256>>>(dbl, W_dt, b_dt, dtp);
    // 6) selective scan v2 + chunk-level gate
    scan2_k<<<dim3(DIN / 16, BB), 256>>>(dtp, xm, dbl, A_log, xz, D_par, yg);
    // 7) x2 = yg @ W_out + res
    bf16gemm_k<1><<<dim3(CC / 128, MM / 128), 256>>>(yg, W_out, x2, MM, CC, DIN, nullptr, xt);
    // 8) LN2
    layernorm_k<<<MM, 256>>>(x2, xn2, ln2_g, ln2_b);
    // 9) h1 = gelu(xn2 @ W1 + b1)
    bf16gemm_k<2><<<dim3(HID / 128, MM / 128), 256>>>(xn2, W1, h1, MM, HID, CC, b1, nullptr);
    // 10) x3 = h1 @ W2 + b2 + x2
    bf16gemm_k<3><<<dim3(CC / 128, MM / 128), 256>>>(h1, W2, x3, MM, CC, HID, b2, x2);
    // 11) transpose back (B,L,C) -> (B,C,L)
    transpose_k<<<dim3(CC / 32, LL / 32, BB), dim3(32, 8)>>>(x3, out, LL, CC);
}

// round 15
// speedup vs baseline: 1.5576x; 1.5576x over previous
#include <cuda_runtime.h>
#include <math.h>
#include <stdint.h>

// Problem constants
#define BB   8
#define CC   256
#define LL   1024          // H*W
#define DIN  512           // d_inner
#define DST  16            // d_state
#define RANK 16
#define HID  1024
#define MM   (BB*LL)       // 8192 tokens
#define DBLS 128           // padded dbl row stride

// ---------------- scratch (device globals; no allocation APIs) -------------
__device__ float g_xt [MM*CC];     // x transposed (B,L,C) == residual 1
__device__ float g_xn [MM*CC];     // LN1 out
__device__ float g_xz [MM*2*DIN];  // xn @ W_in
__device__ float g_xm [MM*DIN];    // conv+silu out
__device__ float g_dbl[MM*DBLS];   // xm @ W_x padded (dt_raw | B | C | 0..)
__device__ float g_wxp[DIN*DBLS];  // W_x zero-padded to 512x128
__device__ float g_dt [MM*DIN];    // softplus(dt_raw @ W_dt + b_dt)
__device__ float g_yg [MM*DIN];    // gated scan output
__device__ float g_x2 [MM*CC];     // mamba out + res (residual 2)
__device__ float g_xn2[MM*CC];     // LN2 out
__device__ float g_h1 [MM*HID];    // gelu(xn2@W1+b1)
__device__ float g_x3 [MM*CC];     // final (B,L,C) before transpose

// ---------------- batched 2D transpose: (b,R,C) -> (b,C,R) -----------------
__global__ void transpose_k(const float* __restrict__ in, float* __restrict__ out,
                            int R, int Cc) {
    __shared__ float t[32][33];
    int b  = blockIdx.z;
    int r0 = blockIdx.y * 32, c0 = blockIdx.x * 32;
    const float* ib = in  + (size_t)b * R * Cc;
    float*       ob = out + (size_t)b * R * Cc;
#pragma unroll
    for (int i = 0; i < 32; i += 8)
        t[threadIdx.y + i][threadIdx.x] = ib[(r0 + threadIdx.y + i) * Cc + c0 + threadIdx.x];
    __syncthreads();
#pragma unroll
    for (int i = 0; i < 32; i += 8)
        ob[(c0 + threadIdx.y + i) * R + r0 + threadIdx.x] = t[threadIdx.x][threadIdx.y + i];
}

// -------- fused transpose (B,C,L)->(B,L,C) + LayerNorm over C --------------
__global__ __launch_bounds__(256)
void trln_k(const float* __restrict__ in, float* __restrict__ xt,
            float* __restrict__ xn, const float* __restrict__ g,
            const float* __restrict__ bt) {
    __shared__ float t[CC][33];
    __shared__ float ps[8][32], psq[8][32];
    __shared__ float mu[32], rs[32];
    int tx = threadIdx.x, ty = threadIdx.y;   // (32, 8)
    int l0 = blockIdx.x * 32;
    int b  = blockIdx.y;
    const float* ib = in + (size_t)b * CC * LL;

#pragma unroll
    for (int c = ty; c < CC; c += 8)
        t[c][tx] = ib[(size_t)c * LL + l0 + tx];
    __syncthreads();

    float s = 0.f, sq = 0.f;
#pragma unroll
    for (int i = 0; i < 32; i++) {
        float v = t[ty * 32 + i][tx];
        s += v; sq = fmaf(v, v, sq);
    }
    ps[ty][tx] = s; psq[ty][tx] = sq;
    __syncthreads();
    if (ty == 0) {
        float tot = 0.f, totq = 0.f;
#pragma unroll
        for (int i = 0; i < 8; i++) { tot += ps[i][tx]; totq += psq[i][tx]; }
        float m = tot * (1.0f / CC);
        float var = totq * (1.0f / CC) - m * m;
        mu[tx] = m; rs[tx] = rsqrtf(var + 1e-5f);
    }
    __syncthreads();

#pragma unroll
    for (int jj = ty; jj < 32; jj += 8) {
        float m = mu[jj], r = rs[jj];
        size_t base = ((size_t)b * LL + l0 + jj) * CC;
#pragma unroll
        for (int cc = tx; cc < CC; cc += 32) {
            float v = t[cc][jj];
            xt[base + cc] = v;
            xn[base + cc] = (v - m) * r * g[cc] + bt[cc];
        }
    }
}

// ---------------- layernorm over C=256, one block per token (LN2) ----------
__global__ void layernorm_k(const float* __restrict__ in, float* __restrict__ out,
                            const float* __restrict__ g, const float* __restrict__ bt) {
    int row = blockIdx.x;
    int tid = threadIdx.x;          // 256
    float v = in[row * CC + tid];
    float s = v, sq = v * v;
#pragma unroll
    for (int o = 16; o; o >>= 1) {
        s  += __shfl_xor_sync(0xffffffffu, s,  o);
        sq += __shfl_xor_sync(0xffffffffu, sq, o);
    }
    __shared__ float ss[8], ssq[8];
    int w = tid >> 5;
    if ((tid & 31) == 0) { ss[w] = s; ssq[w] = sq; }
    __syncthreads();
    float tot = 0.f, totq = 0.f;
#pragma unroll
    for (int i = 0; i < 8; i++) { tot += ss[i]; totq += ssq[i]; }
    float mu  = tot * (1.0f / CC);
    float var = totq * (1.0f / CC) - mu * mu;
    out[row * CC + tid] = (v - mu) * rsqrtf(var + 1e-5f) * g[tid] + bt[tid];
}

// ---------------- bf16 tensor-core GEMM, serial structure, BK=64 -----------
__device__ __forceinline__ uint32_t pkbf16(float lo, float hi) {
    uint32_t r;
    asm("cvt.rn.bf16x2.f32 %0, %1, %2;" : "=r"(r) : "f"(hi), "f"(lo));
    return r;
}

__device__ __forceinline__ void mma_bf16(float* c, const uint32_t* a,
                                         uint32_t b0, uint32_t b1) {
    asm volatile(
        "mma.sync.aligned.m16n8k16.row.col.f32.bf16.bf16.f32 "
        "{%0,%1,%2,%3}, {%4,%5,%6,%7}, {%8,%9}, {%0,%1,%2,%3};"
        : "+f"(c[0]), "+f"(c[1]), "+f"(c[2]), "+f"(c[3])
        : "r"(a[0]), "r"(a[1]), "r"(a[2]), "r"(a[3]), "r"(b0), "r"(b1));
}

template<int EPI>
__global__ __launch_bounds__(256, 2)
void bf16gemm_k(const float* __restrict__ A, const float* __restrict__ Bm,
                float* __restrict__ Cout, int M, int N, int K,
                const float* __restrict__ bias, const float* __restrict__ res) {
    __shared__ uint32_t As[32][132];   // [k2][m]: bf16x2 packs (2k2, 2k2+1), 64 k
    __shared__ uint32_t Bs[32][132];   // [k2][n]
    int tid  = threadIdx.x;
    int lane = tid & 31, warp = tid >> 5;
    int warpM = warp >> 1, warpN = warp & 1;     // 4 x 2 warps
    int bm = blockIdx.y * 128, bn = blockIdx.x * 128;
    int row4 = lane >> 2, kq = lane & 3;

    float acc[2][8][4];
#pragma unroll
    for (int i = 0; i < 2; i++)
#pragma unroll
        for (int j = 0; j < 8; j++)
#pragma unroll
            for (int q = 0; q < 4; q++) acc[i][j][q] = 0.f;

    for (int k0 = 0; k0 < K; k0 += 64) {
        // load A tile (128 rows x 64 k) -> As[k2][m]
#pragma unroll
        for (int q = 0; q < 8; q++) {
            int idx = tid + 256 * q;
            int r = idx >> 4, c = (idx & 15) << 2;     // c = 0..60
            float4 v = *(const float4*)(A + (size_t)(bm + r) * K + k0 + c);
            As[(c >> 1) + 0][r] = pkbf16(v.x, v.y);
            As[(c >> 1) + 1][r] = pkbf16(v.z, v.w);
        }
        // load B tile (64 k x 128 n) -> Bs[k2][n]: each thread packs 2 k-rows
#pragma unroll
        for (int q = 0; q < 2; q++) {
            int k2 = (tid >> 4) + 16 * q;          // 0..31
            int n8 = (tid & 15) << 3;              // 0..120
            const float* p0 = Bm + (size_t)(k0 + 2 * k2) * N + bn + n8;
            const float* p1 = p0 + N;
            float4 e0 = *(const float4*)(p0);
            float4 e1 = *(const float4*)(p0 + 4);
            float4 o0 = *(const float4*)(p1);
            float4 o1 = *(const float4*)(p1 + 4);
            Bs[k2][n8 + 0] = pkbf16(e0.x, o0.x);
            Bs[k2][n8 + 1] = pkbf16(e0.y, o0.y);
            Bs[k2][n8 + 2] = pkbf16(e0.z, o0.z);
            Bs[k2][n8 + 3] = pkbf16(e0.w, o0.w);
            Bs[k2][n8 + 4] = pkbf16(e1.x, o1.x);
            Bs[k2][n8 + 5] = pkbf16(e1.y, o1.y);
            Bs[k2][n8 + 6] = pkbf16(e1.z, o1.z);
            Bs[k2][n8 + 7] = pkbf16(e1.w, o1.w);
        }
        __syncthreads();
#pragma unroll
        for (int ks2 = 0; ks2 < 4; ks2++) {
            int kb = ks2 * 8;
            uint32_t af[2][4];
#pragma unroll
            for (int mi = 0; mi < 2; mi++) {
                int m0 = warpM * 32 + mi * 16;
                af[mi][0] = As[kb + kq][m0 + row4];
                af[mi][1] = As[kb + kq][m0 + 8 + row4];
                af[mi][2] = As[kb + 4 + kq][m0 + row4];
                af[mi][3] = As[kb + 4 + kq][m0 + 8 + row4];
            }
#pragma unroll
            for (int ni = 0; ni < 8; ni++) {
                int n0 = warpN * 64 + ni * 8;
                uint32_t b0 = Bs[kb + kq][n0 + row4];
                uint32_t b1 = Bs[kb + 4 + kq][n0 + row4];
                mma_bf16(acc[0][ni], af[0], b0, b1);
                mma_bf16(acc[1][ni], af[1], b0, b1);
            }
        }
        __syncthreads();
    }

    // epilogue
#pragma unroll
    for (int mi = 0; mi < 2; mi++) {
        int r0 = bm + warpM * 32 + mi * 16 + row4;
#pragma unroll
        for (int ni = 0; ni < 8; ni++) {
            int col = bn + warpN * 64 + ni * 8 + kq * 2;
#pragma unroll
            for (int half = 0; half < 2; half++) {
                int row = r0 + half * 8;
                float v0 = acc[mi][ni][half * 2 + 0];
                float v1 = acc[mi][ni][half * 2 + 1];
                if (EPI == 1) {
                    v0 += res[(size_t)row * N + col];
                    v1 += res[(size_t)row * N + col + 1];
                }
                if (EPI == 2) {
                    v0 += bias[col];
                    v1 += bias[col + 1];
                    v0 = 0.5f * v0 * (1.0f + erff(v0 * 0.70710678118654752f));
                    v1 = 0.5f * v1 * (1.0f + erff(v1 * 0.70710678118654752f));
                }
                if (EPI == 3) {
                    v0 += bias[col]     + res[(size_t)row * N + col];
                    v1 += bias[col + 1] + res[(size_t)row * N + col + 1];
                }
                float2 o = make_float2(v0, v1);
                *(float2*)(Cout + (size_t)row * N + col) = o;
            }
        }
    }
}

// ---------------- pad W_x (512x48) -> (512x128, zero-filled) ---------------
__global__ void pad_wx_k(const float* __restrict__ Wx, float* __restrict__ Wxp) {
    int idx = blockIdx.x * blockDim.x + threadIdx.x;   // DIN*DBLS
    int k = idx >> 7, n = idx & 127;
    Wxp[idx] = (n < 48) ? Wx[k * 48 + n] : 0.0f;
}

// ---------------- depthwise causal conv1d (d_conv=4) + silu, float4 --------
__global__ void conv_silu_k(const float* __restrict__ xz, const float* __restrict__ cw,
                            const float* __restrict__ cb, float* __restrict__ xm) {
    int idx = blockIdx.x * blockDim.x + threadIdx.x;   // MM*DIN/4 threads
    if (idx >= MM * DIN / 4) return;
    int d4 = (idx & 127) << 2;       // channel group base (0..508)
    int t  = idx >> 7;               // token index b*L + l
    int l  = t & (LL - 1);
    int b  = t >> 10;
    float4 acc = *(const float4*)(cb + d4);
    float4 w0 = *(const float4*)(cw + (d4 + 0) * 4);
    float4 w1 = *(const float4*)(cw + (d4 + 1) * 4);
    float4 w2 = *(const float4*)(cw + (d4 + 2) * 4);
    float4 w3 = *(const float4*)(cw + (d4 + 3) * 4);
    const float* wx[4] = {&w0.x, &w1.x, &w2.x, &w3.x};
#pragma unroll
    for (int k = 0; k < 4; k++) {
        int ls = l + k - 3;
        if (ls >= 0) {
            float4 v = *(const float4*)(xz + ((size_t)((b << 10) + ls)) * (2 * DIN) + d4);
            acc.x = fmaf(v.x, wx[0][k], acc.x);
            acc.y = fmaf(v.y, wx[1][k], acc.y);
            acc.z = fmaf(v.z, wx[2][k], acc.z);
            acc.w = fmaf(v.w, wx[3][k], acc.w);
        }
    }
    acc.x = acc.x / (1.0f + __expf(-acc.x));
    acc.y = acc.y / (1.0f + __expf(-acc.y));
    acc.z = acc.z / (1.0f + __expf(-acc.z));
    acc.w = acc.w / (1.0f + __expf(-acc.w));
    *(float4*)(xm + (size_t)t * DIN + d4) = acc;
}

// -------- dt = softplus(dbl[:, :16] @ W_dt + b_dt), W in registers ---------
__global__ __launch_bounds__(256)
void dt2_k(const float* __restrict__ dbl, const float* __restrict__ Wdt,
           const float* __restrict__ bdt, float* __restrict__ dt) {
    __shared__ float sdt[32][17];
    int m0 = blockIdx.x * 32;
    int tid = threadIdx.x;
#pragma unroll
    for (int q = 0; q < 2; q++) {
        int e = tid + q * 256;
        sdt[e >> 4][e & 15] = dbl[(size_t)(m0 + (e >> 4)) * DBLS + (e & 15)];
    }
    int c0 = tid, c1 = tid + 256;
    float w0[16], w1[16];
#pragma unroll
    for (int k = 0; k < 16; k++) {
        w0[k] = Wdt[k * DIN + c0];
        w1[k] = Wdt[k * DIN + c1];
    }
    float b0v = bdt[c0], b1v = bdt[c1];
    __syncthreads();
#pragma unroll 4
    for (int r = 0; r < 32; r++) {
        float a0 = b0v, a1 = b1v;
#pragma unroll
        for (int k = 0; k < 16; k++) {
            float av = sdt[r][k];
            a0 = fmaf(av, w0[k], a0);
            a1 = fmaf(av, w1[k], a1);
        }
        a0 = (a0 > 20.f) ? a0 : log1pf(__expf(a0));
        a1 = (a1 > 20.f) ? a1 : log1pf(__expf(a1));
        dt[(size_t)(m0 + r) * DIN + c0] = a0;
        dt[(size_t)(m0 + r) * DIN + c1] = a1;
    }
}

// ------ selective scan v2 + chunk-level gate (NOT per-iteration) -----------
__global__ __launch_bounds__(256)
void scan2_k(const float* __restrict__ dt, const float* __restrict__ xm,
             const float* __restrict__ dbl, const float* __restrict__ Alog,
             const float* __restrict__ xz, const float* __restrict__ Dp,
             float* __restrict__ yg) {
    __shared__ float sdt[2][64][16], sxm[2][64][16];
    __shared__ float sB[2][64][16], sC[2][64][16];
    __shared__ float sz[2][64][16];
    __shared__ float sy[64][16];

    int tid  = threadIdx.x;
    int warp = tid >> 5, lane = tid & 31;
    int ch   = lane >> 4, s = lane & 15;
    int wch  = warp * 2 + ch;            // local channel 0..15
    int b    = blockIdx.y;
    int d0   = blockIdx.x * 16;
    int d    = d0 + wch;
    int tb   = b << 10;

    float a = -__expf(Alog[d * DST + s]);
    float h = 0.f;

    int j4 = tid >> 2;                   // token within chunk 0..63
    int i4 = (tid & 3) << 2;             // float4 offset 0,4,8,12
    float4 Dv = *(const float4*)(Dp + d0 + i4);

    {
        size_t t = (size_t)(tb + j4);
        *(float4*)&sdt[0][j4][i4] = *(const float4*)(dt  + t * DIN + d0 + i4);
        *(float4*)&sxm[0][j4][i4] = *(const float4*)(xm  + t * DIN + d0 + i4);
        *(float4*)&sB [0][j4][i4] = *(const float4*)(dbl + t * DBLS + 16 + i4);
        *(float4*)&sC [0][j4][i4] = *(const float4*)(dbl + t * DBLS + 32 + i4);
        *(float4*)&sz [0][j4][i4] = *(const float4*)(xz  + t * (2 * DIN) + DIN + d0 + i4);
    }
    __syncthreads();

    for (int c = 0; c < LL / 64; c++) {
        float4 rd, rx, rb, rc, rz;
        bool more = (c + 1 < LL / 64);
        if (more) {
            size_t t = (size_t)(tb + (c + 1) * 64 + j4);
            rd = *(const float4*)(dt  + t * DIN + d0 + i4);
            rx = *(const float4*)(xm  + t * DIN + d0 + i4);
            rb = *(const float4*)(dbl + t * DBLS + 16 + i4);
            rc = *(const float4*)(dbl + t * DBLS + 32 + i4);
            rz = *(const float4*)(xz  + t * (2 * DIN) + DIN + d0 + i4);
        }
        int buf = c & 1;
#pragma unroll 4
        for (int j = 0; j < 64; j++) {
            float dtv = sdt[buf][j][wch];
            float xv  = sxm[buf][j][wch];
            float Bv  = sB[buf][j][s];
            float Cv  = sC[buf][j][s];
            float dA  = __expf(dtv * a);
            h = fmaf(dA, h, dtv * xv * Bv);
            float p = h * Cv;
            p += __shfl_xor_sync(0xffffffffu, p, 8);
            p += __shfl_xor_sync(0xffffffffu, p, 4);
            p += __shfl_xor_sync(0xffffffffu, p, 2);
            p += __shfl_xor_sync(0xffffffffu, p, 1);
            if (s == 0) sy[j][wch] = p;
        }
        __syncthreads();
        {
            float4 pv = *(float4*)&sy[j4][i4];
            float4 xv = *(float4*)&sxm[buf][j4][i4];
            float4 zv = *(float4*)&sz[buf][j4][i4];
            float4 o;
            o.x = fmaf(xv.x, Dv.x, pv.x) * (zv.x / (1.0f + __expf(-zv.x)));
            o.y = fmaf(xv.y, Dv.y, pv.y) * (zv.y / (1.0f + __expf(-zv.y)));
            o.z = fmaf(xv.z, Dv.z, pv.z) * (zv.z / (1.0f + __expf(-zv.z)));
            o.w = fmaf(xv.w, Dv.w, pv.w) * (zv.w / (1.0f + __expf(-zv.w)));
            size_t t = (size_t)(tb + c * 64 + j4);
            *(float4*)(yg + t * DIN + d0 + i4) = o;
        }
        if (more) {
            int nb = buf ^ 1;
            *(float4*)&sdt[nb][j4][i4] = rd;
            *(float4*)&sxm[nb][j4][i4] = rx;
            *(float4*)&sB [nb][j4][i4] = rb;
            *(float4*)&sC [nb][j4][i4] = rc;
            *(float4*)&sz [nb][j4][i4] = rz;
        }
        __syncthreads();
    }
}

// ---------------------------- launch ---------------------------------------
extern "C" void kernel_launch(void* const* d_in, const int* in_sizes, int n_in,
                              void* d_out, int out_size) {
    const float* x      = (const float*)d_in[0];
    const float* ln1_g  = (const float*)d_in[1];
    const float* ln1_b  = (const float*)d_in[2];
    const float* ln2_g  = (const float*)d_in[3];
    const float* ln2_b  = (const float*)d_in[4];
    const float* W_in   = (const float*)d_in[5];
    const float* conv_w = (const float*)d_in[6];
    const float* conv_b = (const float*)d_in[7];
    const float* W_x    = (const float*)d_in[8];
    const float* W_dt   = (const float*)d_in[9];
    const float* b_dt   = (const float*)d_in[10];
    const float* A_log  = (const float*)d_in[11];
    const float* D_par  = (const float*)d_in[12];
    const float* W_out  = (const float*)d_in[13];
    const float* W1     = (const float*)d_in[14];
    const float* b1     = (const float*)d_in[15];
    const float* W2     = (const float*)d_in[16];
    const float* b2     = (const float*)d_in[17];
    float* out = (float*)d_out;

    float *xt, *xn, *xz, *xm, *dbl, *wxp, *dtp, *yg, *x2, *xn2, *h1, *x3;
    cudaGetSymbolAddress((void**)&xt,  g_xt);
    cudaGetSymbolAddress((void**)&xn,  g_xn);
    cudaGetSymbolAddress((void**)&xz,  g_xz);
    cudaGetSymbolAddress((void**)&xm,  g_xm);
    cudaGetSymbolAddress((void**)&dbl, g_dbl);
    cudaGetSymbolAddress((void**)&wxp, g_wxp);
    cudaGetSymbolAddress((void**)&dtp, g_dt);
    cudaGetSymbolAddress((void**)&yg,  g_yg);
    cudaGetSymbolAddress((void**)&x2,  g_x2);
    cudaGetSymbolAddress((void**)&xn2, g_xn2);
    cudaGetSymbolAddress((void**)&h1,  g_h1);
    cudaGetSymbolAddress((void**)&x3,  g_x3);

    // 1) fused transpose + LN1
    trln_k<<<dim3(LL / 32, BB), dim3(32, 8)>>>(x, xt, xn, ln1_g, ln1_b);
    // 2) xz = xn @ W_in  (bf16, BK=64)
    bf16gemm_k<0><<<dim3((2 * DIN) / 128, MM / 128), 256>>>(xn, W_in, xz, MM, 2 * DIN, CC, nullptr, nullptr);
    // 3) depthwise causal conv + silu
    conv_silu_k<<<(MM * DIN / 4) / 256, 256>>>(xz, conv_w, conv_b, xm);
    // 4) pad W_x, then dbl = xm @ W_x (padded)
    pad_wx_k<<<(DIN * DBLS) / 256, 256>>>(W_x, wxp);
    bf16gemm_k<0><<<dim3(DBLS / 128, MM / 128), 256>>>(xm, wxp, dbl, MM, DBLS, DIN, nullptr, nullptr);
    // 5) dt = softplus(dbl[:, :16] @ W_dt + b_dt)
    dt2_k<<<MM / 32, 256>>>(dbl, W_dt, b_dt, dtp);
    // 6) selective scan v2 + chunk-level gate
    scan2_k<<<dim3(DIN / 16, BB), 256>>>(dtp, xm, dbl, A_log, xz, D_par, yg);
    // 7) x2 = yg @ W_out + res
    bf16gemm_k<1><<<dim3(CC / 128, MM / 128), 256>>>(yg, W_out, x2, MM, CC, DIN, nullptr, xt);
    // 8) LN2
    layernorm_k<<<MM, 256>>>(x2, xn2, ln2_g, ln2_b);
    // 9) h1 = gelu(xn2 @ W1 + b1)
    bf16gemm_k<2><<<dim3(HID / 128, MM / 128), 256>>>(xn2, W1, h1, MM, HID, CC, b1, nullptr);
    // 10) x3 = h1 @ W2 + b2 + x2
    bf16gemm_k<3><<<dim3(CC / 128, MM / 128), 256>>>(h1, W2, x3, MM, CC, HID, b2, x2);
    // 11) transpose back (B,L,C) -> (B,C,L)
    transpose_k<<<dim3(CC / 32, LL / 32, BB), dim3(32, 8)>>>(x3, out, LL, CC);
}

// round 16
// speedup vs baseline: 1.6035x; 1.0294x over previous
#include <cuda_runtime.h>
#include <cuda_bf16.h>
#include <math.h>
#include <stdint.h>

// Problem constants
#define BB   8
#define CC   256
#define LL   1024          // H*W
#define DIN  512           // d_inner
#define DST  16            // d_state
#define RANK 16
#define HID  1024
#define MM   (BB*LL)       // 8192 tokens
#define DBLS 128           // padded dbl row stride

// ---------------- scratch (device globals; no allocation APIs) -------------
__device__ float          g_xt [MM*CC];     // residual 1 (f32)
__device__ __nv_bfloat16  g_xn [MM*CC];     // LN1 out (bf16: GEMM-A only)
__device__ float          g_xz [MM*2*DIN];  // xn @ W_in (f32: conv+scan consume)
__device__ float          g_xm [MM*DIN];    // conv+silu out (f32: scan consumes)
__device__ float          g_dbl[MM*DBLS];   // xm @ W_x padded (f32: scan B/C)
__device__ float          g_wxp[DIN*DBLS];  // W_x zero-padded
__device__ float          g_dt [MM*DIN];    // softplus dt (f32: exp-sensitive)
__device__ __nv_bfloat16  g_yg [MM*DIN];    // gated scan out (bf16: GEMM-A only)
__device__ float          g_x2 [MM*CC];     // residual 2 (f32)
__device__ __nv_bfloat16  g_xn2[MM*CC];     // LN2 out (bf16: GEMM-A only)
__device__ __nv_bfloat16  g_h1 [MM*HID];    // gelu MLP hidden (bf16: GEMM-A only)
__device__ float          g_x3 [MM*CC];     // final (B,L,C) f32

// ---------------- batched 2D transpose: (b,R,C) -> (b,C,R) -----------------
__global__ void transpose_k(const float* __restrict__ in, float* __restrict__ out,
                            int R, int Cc) {
    __shared__ float t[32][33];
    int b  = blockIdx.z;
    int r0 = blockIdx.y * 32, c0 = blockIdx.x * 32;
    const float* ib = in  + (size_t)b * R * Cc;
    float*       ob = out + (size_t)b * R * Cc;
#pragma unroll
    for (int i = 0; i < 32; i += 8)
        t[threadIdx.y + i][threadIdx.x] = ib[(r0 + threadIdx.y + i) * Cc + c0 + threadIdx.x];
    __syncthreads();
#pragma unroll
    for (int i = 0; i < 32; i += 8)
        ob[(c0 + threadIdx.y + i) * R + r0 + threadIdx.x] = t[threadIdx.x][threadIdx.y + i];
}

// -------- fused transpose (B,C,L)->(B,L,C) + LayerNorm over C --------------
__global__ __launch_bounds__(256)
void trln_k(const float* __restrict__ in, float* __restrict__ xt,
            __nv_bfloat16* __restrict__ xn, const float* __restrict__ g,
            const float* __restrict__ bt) {
    __shared__ float t[CC][33];
    __shared__ float ps[8][32], psq[8][32];
    __shared__ float mu[32], rs[32];
    int tx = threadIdx.x, ty = threadIdx.y;   // (32, 8)
    int l0 = blockIdx.x * 32;
    int b  = blockIdx.y;
    const float* ib = in + (size_t)b * CC * LL;

#pragma unroll
    for (int c = ty; c < CC; c += 8)
        t[c][tx] = ib[(size_t)c * LL + l0 + tx];
    __syncthreads();

    float s = 0.f, sq = 0.f;
#pragma unroll
    for (int i = 0; i < 32; i++) {
        float v = t[ty * 32 + i][tx];
        s += v; sq = fmaf(v, v, sq);
    }
    ps[ty][tx] = s; psq[ty][tx] = sq;
    __syncthreads();
    if (ty == 0) {
        float tot = 0.f, totq = 0.f;
#pragma unroll
        for (int i = 0; i < 8; i++) { tot += ps[i][tx]; totq += psq[i][tx]; }
        float m = tot * (1.0f / CC);
        float var = totq * (1.0f / CC) - m * m;
        mu[tx] = m; rs[tx] = rsqrtf(var + 1e-5f);
    }
    __syncthreads();

#pragma unroll
    for (int jj = ty; jj < 32; jj += 8) {
        float m = mu[jj], r = rs[jj];
        size_t base = ((size_t)b * LL + l0 + jj) * CC;
#pragma unroll
        for (int cc = tx; cc < CC; cc += 32) {
            float v = t[cc][jj];
            xt[base + cc] = v;
            xn[base + cc] = __float2bfloat16((v - m) * r * g[cc] + bt[cc]);
        }
    }
}

// ---------------- layernorm over C=256, bf16 out (LN2) ---------------------
__global__ void layernorm_k(const float* __restrict__ in, __nv_bfloat16* __restrict__ out,
                            const float* __restrict__ g, const float* __restrict__ bt) {
    int row = blockIdx.x;
    int tid = threadIdx.x;          // 256
    float v = in[row * CC + tid];
    float s = v, sq = v * v;
#pragma unroll
    for (int o = 16; o; o >>= 1) {
        s  += __shfl_xor_sync(0xffffffffu, s,  o);
        sq += __shfl_xor_sync(0xffffffffu, sq, o);
    }
    __shared__ float ss[8], ssq[8];
    int w = tid >> 5;
    if ((tid & 31) == 0) { ss[w] = s; ssq[w] = sq; }
    __syncthreads();
    float tot = 0.f, totq = 0.f;
#pragma unroll
    for (int i = 0; i < 8; i++) { tot += ss[i]; totq += ssq[i]; }
    float mu  = tot * (1.0f / CC);
    float var = totq * (1.0f / CC) - mu * mu;
    out[row * CC + tid] = __float2bfloat16((v - mu) * rsqrtf(var + 1e-5f) * g[tid] + bt[tid]);
}

// ---------------- bf16 tensor-core GEMM, serial, BK=64 ---------------------
// ABF: A operand stored as bf16 (loads are raw pairs). OBF: output stored bf16.
__device__ __forceinline__ uint32_t pkbf16(float lo, float hi) {
    uint32_t r;
    asm("cvt.rn.bf16x2.f32 %0, %1, %2;" : "=r"(r) : "f"(hi), "f"(lo));
    return r;
}

__device__ __forceinline__ void mma_bf16(float* c, const uint32_t* a,
                                         uint32_t b0, uint32_t b1) {
    asm volatile(
        "mma.sync.aligned.m16n8k16.row.col.f32.bf16.bf16.f32 "
        "{%0,%1,%2,%3}, {%4,%5,%6,%7}, {%8,%9}, {%0,%1,%2,%3};"
        : "+f"(c[0]), "+f"(c[1]), "+f"(c[2]), "+f"(c[3])
        : "r"(a[0]), "r"(a[1]), "r"(a[2]), "r"(a[3]), "r"(b0), "r"(b1));
}

template<int EPI, int ABF, int OBF>
__global__ __launch_bounds__(256, 2)
void bf16gemm_k(const void* __restrict__ Av, const float* __restrict__ Bm,
                void* __restrict__ Cv, int M, int N, int K,
                const float* __restrict__ bias, const float* __restrict__ res) {
    __shared__ uint32_t As[32][132];   // [k2][m]: bf16x2 packs (2k2, 2k2+1), 64 k
    __shared__ uint32_t Bs[32][132];   // [k2][n]
    int tid  = threadIdx.x;
    int lane = tid & 31, warp = tid >> 5;
    int warpM = warp >> 1, warpN = warp & 1;     // 4 x 2 warps
    int bm = blockIdx.y * 128, bn = blockIdx.x * 128;
    int row4 = lane >> 2, kq = lane & 3;

    float acc[2][8][4];
#pragma unroll
    for (int i = 0; i < 2; i++)
#pragma unroll
        for (int j = 0; j < 8; j++)
#pragma unroll
            for (int q = 0; q < 4; q++) acc[i][j][q] = 0.f;

    for (int k0 = 0; k0 < K; k0 += 64) {
        // load A tile (128 rows x 64 k) -> As[k2][m]
        if (ABF) {
            const __nv_bfloat16* Ab = (const __nv_bfloat16*)Av;
#pragma unroll
            for (int q = 0; q < 4; q++) {
                int idx = tid + 256 * q;
                int r = idx >> 3, c = (idx & 7) << 3;   // 8 k per thread-load
                uint4 v = *(const uint4*)(Ab + (size_t)(bm + r) * K + k0 + c);
                As[(c >> 1) + 0][r] = v.x;
                As[(c >> 1) + 1][r] = v.y;
                As[(c >> 1) + 2][r] = v.z;
                As[(c >> 1) + 3][r] = v.w;
            }
        } else {
            const float* Af = (const float*)Av;
#pragma unroll
            for (int q = 0; q < 8; q++) {
                int idx = tid + 256 * q;
                int r = idx >> 4, c = (idx & 15) << 2;
                float4 v = *(const float4*)(Af + (size_t)(bm + r) * K + k0 + c);
                As[(c >> 1) + 0][r] = pkbf16(v.x, v.y);
                As[(c >> 1) + 1][r] = pkbf16(v.z, v.w);
            }
        }
        // load B tile (64 k x 128 n) f32 -> Bs[k2][n]
#pragma unroll
        for (int q = 0; q < 2; q++) {
            int k2 = (tid >> 4) + 16 * q;          // 0..31
            int n8 = (tid & 15) << 3;              // 0..120
            const float* p0 = Bm + (size_t)(k0 + 2 * k2) * N + bn + n8;
            const float* p1 = p0 + N;
            float4 e0 = *(const float4*)(p0);
            float4 e1 = *(const float4*)(p0 + 4);
            float4 o0 = *(const float4*)(p1);
            float4 o1 = *(const float4*)(p1 + 4);
            Bs[k2][n8 + 0] = pkbf16(e0.x, o0.x);
            Bs[k2][n8 + 1] = pkbf16(e0.y, o0.y);
            Bs[k2][n8 + 2] = pkbf16(e0.z, o0.z);
            Bs[k2][n8 + 3] = pkbf16(e0.w, o0.w);
            Bs[k2][n8 + 4] = pkbf16(e1.x, o1.x);
            Bs[k2][n8 + 5] = pkbf16(e1.y, o1.y);
            Bs[k2][n8 + 6] = pkbf16(e1.z, o1.z);
            Bs[k2][n8 + 7] = pkbf16(e1.w, o1.w);
        }
        __syncthreads();
#pragma unroll
        for (int ks2 = 0; ks2 < 4; ks2++) {
            int kb = ks2 * 8;
            uint32_t af[2][4];
#pragma unroll
            for (int mi = 0; mi < 2; mi++) {
                int m0 = warpM * 32 + mi * 16;
                af[mi][0] = As[kb + kq][m0 + row4];
                af[mi][1] = As[kb + kq][m0 + 8 + row4];
                af[mi][2] = As[kb + 4 + kq][m0 + row4];
                af[mi][3] = As[kb + 4 + kq][m0 + 8 + row4];
            }
#pragma unroll
            for (int ni = 0; ni < 8; ni++) {
                int n0 = warpN * 64 + ni * 8;
                uint32_t b0 = Bs[kb + kq][n0 + row4];
                uint32_t b1 = Bs[kb + 4 + kq][n0 + row4];
                mma_bf16(acc[0][ni], af[0], b0, b1);
                mma_bf16(acc[1][ni], af[1], b0, b1);
            }
        }
        __syncthreads();
    }

    // epilogue
#pragma unroll
    for (int mi = 0; mi < 2; mi++) {
        int r0 = bm + warpM * 32 + mi * 16 + row4;
#pragma unroll
        for (int ni = 0; ni < 8; ni++) {
            int col = bn + warpN * 64 + ni * 8 + kq * 2;
#pragma unroll
            for (int half = 0; half < 2; half++) {
                int row = r0 + half * 8;
                float v0 = acc[mi][ni][half * 2 + 0];
                float v1 = acc[mi][ni][half * 2 + 1];
                if (EPI == 1) {
                    v0 += res[(size_t)row * N + col];
                    v1 += res[(size_t)row * N + col + 1];
                }
                if (EPI == 2) {
                    v0 += bias[col];
                    v1 += bias[col + 1];
                    v0 = 0.5f * v0 * (1.0f + erff(v0 * 0.70710678118654752f));
                    v1 = 0.5f * v1 * (1.0f + erff(v1 * 0.70710678118654752f));
                }
                if (EPI == 3) {
                    v0 += bias[col]     + res[(size_t)row * N + col];
                    v1 += bias[col + 1] + res[(size_t)row * N + col + 1];
                }
                if (OBF) {
                    *(uint32_t*)((__nv_bfloat16*)Cv + (size_t)row * N + col) = pkbf16(v0, v1);
                } else {
                    *(float2*)((float*)Cv + (size_t)row * N + col) = make_float2(v0, v1);
                }
            }
        }
    }
}

// ---------------- pad W_x (512x48) -> (512x128, zero-filled) ---------------
__global__ void pad_wx_k(const float* __restrict__ Wx, float* __restrict__ Wxp) {
    int idx = blockIdx.x * blockDim.x + threadIdx.x;   // DIN*DBLS
    int k = idx >> 7, n = idx & 127;
    Wxp[idx] = (n < 48) ? Wx[k * 48 + n] : 0.0f;
}

// ---------------- depthwise causal conv1d (d_conv=4) + silu, float4 --------
__global__ void conv_silu_k(const float* __restrict__ xz, const float* __restrict__ cw,
                            const float* __restrict__ cb, float* __restrict__ xm) {
    int idx = blockIdx.x * blockDim.x + threadIdx.x;   // MM*DIN/4 threads
    if (idx >= MM * DIN / 4) return;
    int d4 = (idx & 127) << 2;       // channel group base (0..508)
    int t  = idx >> 7;               // token index b*L + l
    int l  = t & (LL - 1);
    int b  = t >> 10;
    float4 acc = *(const float4*)(cb + d4);
    float4 w0 = *(const float4*)(cw + (d4 + 0) * 4);
    float4 w1 = *(const float4*)(cw + (d4 + 1) * 4);
    float4 w2 = *(const float4*)(cw + (d4 + 2) * 4);
    float4 w3 = *(const float4*)(cw + (d4 + 3) * 4);
    const float* wx[4] = {&w0.x, &w1.x, &w2.x, &w3.x};
#pragma unroll
    for (int k = 0; k < 4; k++) {
        int ls = l + k - 3;
        if (ls >= 0) {
            float4 v = *(const float4*)(xz + ((size_t)((b << 10) + ls)) * (2 * DIN) + d4);
            acc.x = fmaf(v.x, wx[0][k], acc.x);
            acc.y = fmaf(v.y, wx[1][k], acc.y);
            acc.z = fmaf(v.z, wx[2][k], acc.z);
            acc.w = fmaf(v.w, wx[3][k], acc.w);
        }
    }
    acc.x = acc.x / (1.0f + __expf(-acc.x));
    acc.y = acc.y / (1.0f + __expf(-acc.y));
    acc.z = acc.z / (1.0f + __expf(-acc.z));
    acc.w = acc.w / (1.0f + __expf(-acc.w));
    *(float4*)(xm + (size_t)t * DIN + d4) = acc;
}

// -------- dt = softplus(dbl[:, :16] @ W_dt + b_dt), W in registers ---------
__global__ __launch_bounds__(256)
void dt2_k(const float* __restrict__ dbl, const float* __restrict__ Wdt,
           const float* __restrict__ bdt, float* __restrict__ dt) {
    __shared__ float sdt[32][17];
    int m0 = blockIdx.x * 32;
    int tid = threadIdx.x;
#pragma unroll
    for (int q = 0; q < 2; q++) {
        int e = tid + q * 256;
        sdt[e >> 4][e & 15] = dbl[(size_t)(m0 + (e >> 4)) * DBLS + (e & 15)];
    }
    int c0 = tid, c1 = tid + 256;
    float w0[16], w1[16];
#pragma unroll
    for (int k = 0; k < 16; k++) {
        w0[k] = Wdt[k * DIN + c0];
        w1[k] = Wdt[k * DIN + c1];
    }
    float b0v = bdt[c0], b1v = bdt[c1];
    __syncthreads();
#pragma unroll 4
    for (int r = 0; r < 32; r++) {
        float a0 = b0v, a1 = b1v;
#pragma unroll
        for (int k = 0; k < 16; k++) {
            float av = sdt[r][k];
            a0 = fmaf(av, w0[k], a0);
            a1 = fmaf(av, w1[k], a1);
        }
        a0 = (a0 > 20.f) ? a0 : log1pf(__expf(a0));
        a1 = (a1 > 20.f) ? a1 : log1pf(__expf(a1));
        dt[(size_t)(m0 + r) * DIN + c0] = a0;
        dt[(size_t)(m0 + r) * DIN + c1] = a1;
    }
}

// ------ selective scan v2 + chunk-level gate; yg stored bf16 ---------------
__global__ __launch_bounds__(256)
void scan2_k(const float* __restrict__ dt, const float* __restrict__ xm,
             const float* __restrict__ dbl, const float* __restrict__ Alog,
             const float* __restrict__ xz, const float* __restrict__ Dp,
             __nv_bfloat16* __restrict__ yg) {
    __shared__ float sdt[2][64][16], sxm[2][64][16];
    __shared__ float sB[2][64][16], sC[2][64][16];
    __shared__ float sz[2][64][16];
    __shared__ float sy[64][16];

    int tid  = threadIdx.x;
    int warp = tid >> 5, lane = tid & 31;
    int ch   = lane >> 4, s = lane & 15;
    int wch  = warp * 2 + ch;            // local channel 0..15
    int b    = blockIdx.y;
    int d0   = blockIdx.x * 16;
    int d    = d0 + wch;
    int tb   = b << 10;

    float a = -__expf(Alog[d * DST + s]);
    float h = 0.f;

    int j4 = tid >> 2;                   // token within chunk 0..63
    int i4 = (tid & 3) << 2;             // float4 offset 0,4,8,12
    float4 Dv = *(const float4*)(Dp + d0 + i4);

    {
        size_t t = (size_t)(tb + j4);
        *(float4*)&sdt[0][j4][i4] = *(const float4*)(dt  + t * DIN + d0 + i4);
        *(float4*)&sxm[0][j4][i4] = *(const float4*)(xm  + t * DIN + d0 + i4);
        *(float4*)&sB [0][j4][i4] = *(const float4*)(dbl + t * DBLS + 16 + i4);
        *(float4*)&sC [0][j4][i4] = *(const float4*)(dbl + t * DBLS + 32 + i4);
        *(float4*)&sz [0][j4][i4] = *(const float4*)(xz  + t * (2 * DIN) + DIN + d0 + i4);
    }
    __syncthreads();

    for (int c = 0; c < LL / 64; c++) {
        float4 rd, rx, rb, rc, rz;
        bool more = (c + 1 < LL / 64);
        if (more) {
            size_t t = (size_t)(tb + (c + 1) * 64 + j4);
            rd = *(const float4*)(dt  + t * DIN + d0 + i4);
            rx = *(const float4*)(xm  + t * DIN + d0 + i4);
            rb = *(const float4*)(dbl + t * DBLS + 16 + i4);
            rc = *(const float4*)(dbl + t * DBLS + 32 + i4);
            rz = *(const float4*)(xz  + t * (2 * DIN) + DIN + d0 + i4);
        }
        int buf = c & 1;
#pragma unroll 4
        for (int j = 0; j < 64; j++) {
            float dtv = sdt[buf][j][wch];
            float xv  = sxm[buf][j][wch];
            float Bv  = sB[buf][j][s];
            float Cv  = sC[buf][j][s];
            float dA  = __expf(dtv * a);
            h = fmaf(dA, h, dtv * xv * Bv);
            float p = h * Cv;
            p += __shfl_xor_sync(0xffffffffu, p, 8);
            p += __shfl_xor_sync(0xffffffffu, p, 4);
            p += __shfl_xor_sync(0xffffffffu, p, 2);
            p += __shfl_xor_sync(0xffffffffu, p, 1);
            if (s == 0) sy[j][wch] = p;
        }
        __syncthreads();
        {
            float4 pv = *(float4*)&sy[j4][i4];
            float4 xv = *(float4*)&sxm[buf][j4][i4];
            float4 zv = *(float4*)&sz[buf][j4][i4];
            float o0 = fmaf(xv.x, Dv.x, pv.x) * (zv.x / (1.0f + __expf(-zv.x)));
            float o1 = fmaf(xv.y, Dv.y, pv.y) * (zv.y / (1.0f + __expf(-zv.y)));
            float o2 = fmaf(xv.z, Dv.z, pv.z) * (zv.z / (1.0f + __expf(-zv.z)));
            float o3 = fmaf(xv.w, Dv.w, pv.w) * (zv.w / (1.0f + __expf(-zv.w)));
            uint2 packed;
            packed.x = pkbf16(o0, o1);
            packed.y = pkbf16(o2, o3);
            size_t t = (size_t)(tb + c * 64 + j4);
            *(uint2*)(yg + t * DIN + d0 + i4) = packed;
        }
        if (more) {
            int nb = buf ^ 1;
            *(float4*)&sdt[nb][j4][i4] = rd;
            *(float4*)&sxm[nb][j4][i4] = rx;
            *(float4*)&sB [nb][j4][i4] = rb;
            *(float4*)&sC [nb][j4][i4] = rc;
            *(float4*)&sz [nb][j4][i4] = rz;
        }
        __syncthreads();
    }
}

// ---------------------------- launch ---------------------------------------
extern "C" void kernel_launch(void* const* d_in, const int* in_sizes, int n_in,
                              void* d_out, int out_size) {
    const float* x      = (const float*)d_in[0];
    const float* ln1_g  = (const float*)d_in[1];
    const float* ln1_b  = (const float*)d_in[2];
    const float* ln2_g  = (const float*)d_in[3];
    const float* ln2_b  = (const float*)d_in[4];
    const float* W_in   = (const float*)d_in[5];
    const float* conv_w = (const float*)d_in[6];
    const float* conv_b = (const float*)d_in[7];
    const float* W_x    = (const float*)d_in[8];
    const float* W_dt   = (const float*)d_in[9];
    const float* b_dt   = (const float*)d_in[10];
    const float* A_log  = (const float*)d_in[11];
    const float* D_par  = (const float*)d_in[12];
    const float* W_out  = (const float*)d_in[13];
    const float* W1     = (const float*)d_in[14];
    const float* b1     = (const float*)d_in[15];
    const float* W2     = (const float*)d_in[16];
    const float* b2     = (const float*)d_in[17];
    float* out = (float*)d_out;

    float *xt, *xz, *xm, *dbl, *wxp, *dtp, *x2, *x3;
    __nv_bfloat16 *xn, *yg, *xn2, *h1;
    cudaGetSymbolAddress((void**)&xt,  g_xt);
    cudaGetSymbolAddress((void**)&xn,  g_xn);
    cudaGetSymbolAddress((void**)&xz,  g_xz);
    cudaGetSymbolAddress((void**)&xm,  g_xm);
    cudaGetSymbolAddress((void**)&dbl, g_dbl);
    cudaGetSymbolAddress((void**)&wxp, g_wxp);
    cudaGetSymbolAddress((void**)&dtp, g_dt);
    cudaGetSymbolAddress((void**)&yg,  g_yg);
    cudaGetSymbolAddress((void**)&x2,  g_x2);
    cudaGetSymbolAddress((void**)&xn2, g_xn2);
    cudaGetSymbolAddress((void**)&h1,  g_h1);
    cudaGetSymbolAddress((void**)&x3,  g_x3);

    // 0) pad W_x (independent; issued first)
    pad_wx_k<<<(DIN * DBLS) / 256, 256>>>(W_x, wxp);
    // 1) fused transpose + LN1 (xn -> bf16)
    trln_k<<<dim3(LL / 32, BB), dim3(32, 8)>>>(x, xt, xn, ln1_g, ln1_b);
    // 2) xz = xn @ W_in  (A bf16, out f32)
    bf16gemm_k<0, 1, 0><<<dim3((2 * DIN) / 128, MM / 128), 256>>>(xn, W_in, xz, MM, 2 * DIN, CC, nullptr, nullptr);
    // 3) depthwise causal conv + silu
    conv_silu_k<<<(MM * DIN / 4) / 256, 256>>>(xz, conv_w, conv_b, xm);
    // 4) dbl = xm @ W_x (A f32, out f32)
    bf16gemm_k<0, 0, 0><<<dim3(DBLS / 128, MM / 128), 256>>>(xm, wxp, dbl, MM, DBLS, DIN, nullptr, nullptr);
    // 5) dt = softplus(dbl[:, :16] @ W_dt + b_dt)
    dt2_k<<<MM / 32, 256>>>(dbl, W_dt, b_dt, dtp);
    // 6) selective scan v2 + chunk-level gate (yg -> bf16)
    scan2_k<<<dim3(DIN / 16, BB), 256>>>(dtp, xm, dbl, A_log, xz, D_par, yg);
    // 7) x2 = yg @ W_out + res  (A bf16, out f32)
    bf16gemm_k<1, 1, 0><<<dim3(CC / 128, MM / 128), 256>>>(yg, W_out, x2, MM, CC, DIN, nullptr, xt);
    // 8) LN2 (xn2 -> bf16)
    layernorm_k<<<MM, 256>>>(x2, xn2, ln2_g, ln2_b);
    // 9) h1 = gelu(xn2 @ W1 + b1)  (A bf16, out bf16)
    bf16gemm_k<2, 1, 1><<<dim3(HID / 128, MM / 128), 256>>>(xn2, W1, h1, MM, HID, CC, b1, nullptr);
    // 10) x3 = h1 @ W2 + b2 + x2  (A bf16, out f32)
    bf16gemm_k<3, 1, 0><<<dim3(CC / 128, MM / 128), 256>>>(h1, W2, x3, MM, CC, HID, b2, x2);
    // 11) transpose back (B,L,C) -> (B,C,L)
    transpose_k<<<dim3(CC / 32, LL / 32, BB), dim3(32, 8)>>>(x3, out, LL, CC);
}

// round 17
// speedup vs baseline: 1.6298x; 1.0164x over previous
#include <cuda_runtime.h>
#include <cuda_bf16.h>
#include <math.h>
#include <stdint.h>

// Problem constants
#define BB   8
#define CC   256
#define LL   1024          // H*W
#define DIN  512           // d_inner
#define DST  16            // d_state
#define RANK 16
#define HID  1024
#define MM   (BB*LL)       // 8192 tokens
#define DBLS 128           // padded dbl row stride

// ---------------- scratch (device globals; no allocation APIs) -------------
__device__ float          g_xt [MM*CC];     // residual 1 (f32)
__device__ __nv_bfloat16  g_xn [MM*CC];     // LN1 out (bf16)
__device__ float          g_xz [MM*2*DIN];  // xn @ W_in (f32: conv+scan z)
__device__ __nv_bfloat16  g_xm [MM*DIN];    // conv+silu out (bf16)
__device__ float          g_dbl[MM*DBLS];   // xm @ W_x padded (dtraw | B | C)
__device__ float          g_wxp[DIN*DBLS];  // W_x zero-padded
__device__ __nv_bfloat16  g_yg [MM*DIN];    // gated scan out (bf16)
__device__ float          g_x2 [MM*CC];     // residual 2 (f32)
__device__ __nv_bfloat16  g_xn2[MM*CC];     // LN2 out (bf16)
__device__ __nv_bfloat16  g_h1 [MM*HID];    // MLP hidden (bf16)
__device__ float          g_x3 [MM*CC];     // final (B,L,C) f32

// ---------------- batched 2D transpose: (b,R,C) -> (b,C,R) -----------------
__global__ void transpose_k(const float* __restrict__ in, float* __restrict__ out,
                            int R, int Cc) {
    __shared__ float t[32][33];
    int b  = blockIdx.z;
    int r0 = blockIdx.y * 32, c0 = blockIdx.x * 32;
    const float* ib = in  + (size_t)b * R * Cc;
    float*       ob = out + (size_t)b * R * Cc;
#pragma unroll
    for (int i = 0; i < 32; i += 8)
        t[threadIdx.y + i][threadIdx.x] = ib[(r0 + threadIdx.y + i) * Cc + c0 + threadIdx.x];
    __syncthreads();
#pragma unroll
    for (int i = 0; i < 32; i += 8)
        ob[(c0 + threadIdx.y + i) * R + r0 + threadIdx.x] = t[threadIdx.x][threadIdx.y + i];
}

// -------- fused transpose (B,C,L)->(B,L,C) + LayerNorm over C --------------
__global__ __launch_bounds__(256)
void trln_k(const float* __restrict__ in, float* __restrict__ xt,
            __nv_bfloat16* __restrict__ xn, const float* __restrict__ g,
            const float* __restrict__ bt) {
    __shared__ float t[CC][33];
    __shared__ float ps[8][32], psq[8][32];
    __shared__ float mu[32], rs[32];
    int tx = threadIdx.x, ty = threadIdx.y;   // (32, 8)
    int l0 = blockIdx.x * 32;
    int b  = blockIdx.y;
    const float* ib = in + (size_t)b * CC * LL;

#pragma unroll
    for (int c = ty; c < CC; c += 8)
        t[c][tx] = ib[(size_t)c * LL + l0 + tx];
    __syncthreads();

    float s = 0.f, sq = 0.f;
#pragma unroll
    for (int i = 0; i < 32; i++) {
        float v = t[ty * 32 + i][tx];
        s += v; sq = fmaf(v, v, sq);
    }
    ps[ty][tx] = s; psq[ty][tx] = sq;
    __syncthreads();
    if (ty == 0) {
        float tot = 0.f, totq = 0.f;
#pragma unroll
        for (int i = 0; i < 8; i++) { tot += ps[i][tx]; totq += psq[i][tx]; }
        float m = tot * (1.0f / CC);
        float var = totq * (1.0f / CC) - m * m;
        mu[tx] = m; rs[tx] = rsqrtf(var + 1e-5f);
    }
    __syncthreads();

#pragma unroll
    for (int jj = ty; jj < 32; jj += 8) {
        float m = mu[jj], r = rs[jj];
        size_t base = ((size_t)b * LL + l0 + jj) * CC;
#pragma unroll
        for (int cc = tx; cc < CC; cc += 32) {
            float v = t[cc][jj];
            xt[base + cc] = v;
            xn[base + cc] = __float2bfloat16((v - m) * r * g[cc] + bt[cc]);
        }
    }
}

// ---------------- layernorm over C=256, bf16 out (LN2) ---------------------
__global__ void layernorm_k(const float* __restrict__ in, __nv_bfloat16* __restrict__ out,
                            const float* __restrict__ g, const float* __restrict__ bt) {
    int row = blockIdx.x;
    int tid = threadIdx.x;          // 256
    float v = in[row * CC + tid];
    float s = v, sq = v * v;
#pragma unroll
    for (int o = 16; o; o >>= 1) {
        s  += __shfl_xor_sync(0xffffffffu, s,  o);
        sq += __shfl_xor_sync(0xffffffffu, sq, o);
    }
    __shared__ float ss[8], ssq[8];
    int w = tid >> 5;
    if ((tid & 31) == 0) { ss[w] = s; ssq[w] = sq; }
    __syncthreads();
    float tot = 0.f, totq = 0.f;
#pragma unroll
    for (int i = 0; i < 8; i++) { tot += ss[i]; totq += ssq[i]; }
    float mu  = tot * (1.0f / CC);
    float var = totq * (1.0f / CC) - mu * mu;
    out[row * CC + tid] = __float2bfloat16((v - mu) * rsqrtf(var + 1e-5f) * g[tid] + bt[tid]);
}

// ---------------- bf16 tensor-core GEMM, serial, BK=64 ---------------------
__device__ __forceinline__ uint32_t pkbf16(float lo, float hi) {
    uint32_t r;
    asm("cvt.rn.bf16x2.f32 %0, %1, %2;" : "=r"(r) : "f"(hi), "f"(lo));
    return r;
}

__device__ __forceinline__ void mma_bf16(float* c, const uint32_t* a,
                                         uint32_t b0, uint32_t b1) {
    asm volatile(
        "mma.sync.aligned.m16n8k16.row.col.f32.bf16.bf16.f32 "
        "{%0,%1,%2,%3}, {%4,%5,%6,%7}, {%8,%9}, {%0,%1,%2,%3};"
        : "+f"(c[0]), "+f"(c[1]), "+f"(c[2]), "+f"(c[3])
        : "r"(a[0]), "r"(a[1]), "r"(a[2]), "r"(a[3]), "r"(b0), "r"(b1));
}

template<int EPI, int ABF, int OBF>
__global__ __launch_bounds__(256, 2)
void bf16gemm_k(const void* __restrict__ Av, const float* __restrict__ Bm,
                void* __restrict__ Cv, int M, int N, int K,
                const float* __restrict__ bias, const float* __restrict__ res) {
    __shared__ uint32_t As[32][132];
    __shared__ uint32_t Bs[32][132];
    int tid  = threadIdx.x;
    int lane = tid & 31, warp = tid >> 5;
    int warpM = warp >> 1, warpN = warp & 1;
    int bm = blockIdx.y * 128, bn = blockIdx.x * 128;
    int row4 = lane >> 2, kq = lane & 3;

    float acc[2][8][4];
#pragma unroll
    for (int i = 0; i < 2; i++)
#pragma unroll
        for (int j = 0; j < 8; j++)
#pragma unroll
            for (int q = 0; q < 4; q++) acc[i][j][q] = 0.f;

    for (int k0 = 0; k0 < K; k0 += 64) {
        if (ABF) {
            const __nv_bfloat16* Ab = (const __nv_bfloat16*)Av;
#pragma unroll
            for (int q = 0; q < 4; q++) {
                int idx = tid + 256 * q;
                int r = idx >> 3, c = (idx & 7) << 3;
                uint4 v = *(const uint4*)(Ab + (size_t)(bm + r) * K + k0 + c);
                As[(c >> 1) + 0][r] = v.x;
                As[(c >> 1) + 1][r] = v.y;
                As[(c >> 1) + 2][r] = v.z;
                As[(c >> 1) + 3][r] = v.w;
            }
        } else {
            const float* Af = (const float*)Av;
#pragma unroll
            for (int q = 0; q < 8; q++) {
                int idx = tid + 256 * q;
                int r = idx >> 4, c = (idx & 15) << 2;
                float4 v = *(const float4*)(Af + (size_t)(bm + r) * K + k0 + c);
                As[(c >> 1) + 0][r] = pkbf16(v.x, v.y);
                As[(c >> 1) + 1][r] = pkbf16(v.z, v.w);
            }
        }
#pragma unroll
        for (int q = 0; q < 2; q++) {
            int k2 = (tid >> 4) + 16 * q;
            int n8 = (tid & 15) << 3;
            const float* p0 = Bm + (size_t)(k0 + 2 * k2) * N + bn + n8;
            const float* p1 = p0 + N;
            float4 e0 = *(const float4*)(p0);
            float4 e1 = *(const float4*)(p0 + 4);
            float4 o0 = *(const float4*)(p1);
            float4 o1 = *(const float4*)(p1 + 4);
            Bs[k2][n8 + 0] = pkbf16(e0.x, o0.x);
            Bs[k2][n8 + 1] = pkbf16(e0.y, o0.y);
            Bs[k2][n8 + 2] = pkbf16(e0.z, o0.z);
            Bs[k2][n8 + 3] = pkbf16(e0.w, o0.w);
            Bs[k2][n8 + 4] = pkbf16(e1.x, o1.x);
            Bs[k2][n8 + 5] = pkbf16(e1.y, o1.y);
            Bs[k2][n8 + 6] = pkbf16(e1.z, o1.z);
            Bs[k2][n8 + 7] = pkbf16(e1.w, o1.w);
        }
        __syncthreads();
#pragma unroll
        for (int ks2 = 0; ks2 < 4; ks2++) {
            int kb = ks2 * 8;
            uint32_t af[2][4];
#pragma unroll
            for (int mi = 0; mi < 2; mi++) {
                int m0 = warpM * 32 + mi * 16;
                af[mi][0] = As[kb + kq][m0 + row4];
                af[mi][1] = As[kb + kq][m0 + 8 + row4];
                af[mi][2] = As[kb + 4 + kq][m0 + row4];
                af[mi][3] = As[kb + 4 + kq][m0 + 8 + row4];
            }
#pragma unroll
            for (int ni = 0; ni < 8; ni++) {
                int n0 = warpN * 64 + ni * 8;
                uint32_t b0 = Bs[kb + kq][n0 + row4];
                uint32_t b1 = Bs[kb + 4 + kq][n0 + row4];
                mma_bf16(acc[0][ni], af[0], b0, b1);
                mma_bf16(acc[1][ni], af[1], b0, b1);
            }
        }
        __syncthreads();
    }

#pragma unroll
    for (int mi = 0; mi < 2; mi++) {
        int r0 = bm + warpM * 32 + mi * 16 + row4;
#pragma unroll
        for (int ni = 0; ni < 8; ni++) {
            int col = bn + warpN * 64 + ni * 8 + kq * 2;
#pragma unroll
            for (int half = 0; half < 2; half++) {
                int row = r0 + half * 8;
                float v0 = acc[mi][ni][half * 2 + 0];
                float v1 = acc[mi][ni][half * 2 + 1];
                if (EPI == 1) {
                    v0 += res[(size_t)row * N + col];
                    v1 += res[(size_t)row * N + col + 1];
                }
                if (EPI == 2) {
                    v0 += bias[col];
                    v1 += bias[col + 1];
                    v0 = 0.5f * v0 * (1.0f + erff(v0 * 0.70710678118654752f));
                    v1 = 0.5f * v1 * (1.0f + erff(v1 * 0.70710678118654752f));
                }
                if (EPI == 3) {
                    v0 += bias[col]     + res[(size_t)row * N + col];
                    v1 += bias[col + 1] + res[(size_t)row * N + col + 1];
                }
                if (OBF) {
                    *(uint32_t*)((__nv_bfloat16*)Cv + (size_t)row * N + col) = pkbf16(v0, v1);
                } else {
                    *(float2*)((float*)Cv + (size_t)row * N + col) = make_float2(v0, v1);
                }
            }
        }
    }
}

// ---------------- pad W_x (512x48) -> (512x128, zero-filled) ---------------
__global__ void pad_wx_k(const float* __restrict__ Wx, float* __restrict__ Wxp) {
    int idx = blockIdx.x * blockDim.x + threadIdx.x;
    int k = idx >> 7, n = idx & 127;
    Wxp[idx] = (n < 48) ? Wx[k * 48 + n] : 0.0f;
}

// ------- depthwise causal conv1d (d_conv=4) + silu, bf16 out ---------------
__global__ void conv_silu_k(const float* __restrict__ xz, const float* __restrict__ cw,
                            const float* __restrict__ cb, __nv_bfloat16* __restrict__ xm) {
    int idx = blockIdx.x * blockDim.x + threadIdx.x;
    if (idx >= MM * DIN / 4) return;
    int d4 = (idx & 127) << 2;
    int t  = idx >> 7;
    int l  = t & (LL - 1);
    int b  = t >> 10;
    float4 acc = *(const float4*)(cb + d4);
    float4 w0 = *(const float4*)(cw + (d4 + 0) * 4);
    float4 w1 = *(const float4*)(cw + (d4 + 1) * 4);
    float4 w2 = *(const float4*)(cw + (d4 + 2) * 4);
    float4 w3 = *(const float4*)(cw + (d4 + 3) * 4);
    const float* wx[4] = {&w0.x, &w1.x, &w2.x, &w3.x};
#pragma unroll
    for (int k = 0; k < 4; k++) {
        int ls = l + k - 3;
        if (ls >= 0) {
            float4 v = *(const float4*)(xz + ((size_t)((b << 10) + ls)) * (2 * DIN) + d4);
            acc.x = fmaf(v.x, wx[0][k], acc.x);
            acc.y = fmaf(v.y, wx[1][k], acc.y);
            acc.z = fmaf(v.z, wx[2][k], acc.z);
            acc.w = fmaf(v.w, wx[3][k], acc.w);
        }
    }
    acc.x = acc.x / (1.0f + __expf(-acc.x));
    acc.y = acc.y / (1.0f + __expf(-acc.y));
    acc.z = acc.z / (1.0f + __expf(-acc.z));
    acc.w = acc.w / (1.0f + __expf(-acc.w));
    uint2 packed;
    packed.x = pkbf16(acc.x, acc.y);
    packed.y = pkbf16(acc.z, acc.w);
    *(uint2*)(xm + (size_t)t * DIN + d4) = packed;
}

// ------ selective scan v3: fused dt (chunk phase) + chunk-level gate -------
// Block = one batch x 16 channels; chunks of 64 tokens double-buffered.
// dt computed per-chunk from dbl[:, :16] with this block's 16 W_dt columns.
__global__ __launch_bounds__(256)
void scan3_k(const __nv_bfloat16* __restrict__ xm, const float* __restrict__ dbl,
             const float* __restrict__ Alog, const float* __restrict__ xz,
             const float* __restrict__ Dp, const float* __restrict__ Wdt,
             const float* __restrict__ bdt, __nv_bfloat16* __restrict__ yg) {
    __shared__ float sdtr[2][64][17];    // dt_raw (dbl[:, :16]); padded rows
    __shared__ float sxm[2][64][16];
    __shared__ float sB[2][64][16], sC[2][64][16];
    __shared__ float sz[2][64][16];
    __shared__ float sdtv[64][17];       // softplus(dt) for this chunk
    __shared__ float sy[64][16];
    __shared__ float swdt[16][17];       // W_dt columns for this block
    __shared__ float sbias[16];

    int tid  = threadIdx.x;
    int warp = tid >> 5, lane = tid & 31;
    int ch   = lane >> 4, s = lane & 15;
    int wch  = warp * 2 + ch;            // local channel 0..15
    int b    = blockIdx.y;
    int d0   = blockIdx.x * 16;
    int d    = d0 + wch;
    int tb   = b << 10;

    float a = -__expf(Alog[d * DST + s]);
    float h = 0.f;

    int j4 = tid >> 2;                   // token within chunk 0..63
    int i4 = (tid & 3) << 2;             // offset 0,4,8,12
    float4 Dv = *(const float4*)(Dp + d0 + i4);

    // load W_dt columns + bias for this block's channels
    if (tid < 256) {
        int k = tid >> 4, c = tid & 15;
        swdt[k][c] = Wdt[k * DIN + d0 + c];
    }
    if (tid < 16) sbias[tid] = bdt[d0 + tid];

    // preload chunk 0
    {
        size_t t = (size_t)(tb + j4);
        float4 dr = *(const float4*)(dbl + t * DBLS + 0 + i4);
        sdtr[0][j4][i4 + 0] = dr.x; sdtr[0][j4][i4 + 1] = dr.y;
        sdtr[0][j4][i4 + 2] = dr.z; sdtr[0][j4][i4 + 3] = dr.w;
        uint2 xv = *(const uint2*)(xm + t * DIN + d0 + i4);
        float2 xlo = __bfloat1622float2(*(__nv_bfloat162*)&xv.x);
        float2 xhi = __bfloat1622float2(*(__nv_bfloat162*)&xv.y);
        sxm[0][j4][i4 + 0] = xlo.x; sxm[0][j4][i4 + 1] = xlo.y;
        sxm[0][j4][i4 + 2] = xhi.x; sxm[0][j4][i4 + 3] = xhi.y;
        *(float4*)&sB[0][j4][i4] = *(const float4*)(dbl + t * DBLS + 16 + i4);
        *(float4*)&sC[0][j4][i4] = *(const float4*)(dbl + t * DBLS + 32 + i4);
        *(float4*)&sz[0][j4][i4] = *(const float4*)(xz + t * (2 * DIN) + DIN + d0 + i4);
    }
    __syncthreads();

    for (int c = 0; c < LL / 64; c++) {
        float4 rd, rb, rc, rz;
        uint2 rxm;
        bool more = (c + 1 < LL / 64);
        if (more) {
            size_t t = (size_t)(tb + (c + 1) * 64 + j4);
            rd  = *(const float4*)(dbl + t * DBLS + 0 + i4);
            rxm = *(const uint2*)(xm + t * DIN + d0 + i4);
            rb  = *(const float4*)(dbl + t * DBLS + 16 + i4);
            rc  = *(const float4*)(dbl + t * DBLS + 32 + i4);
            rz  = *(const float4*)(xz + t * (2 * DIN) + DIN + d0 + i4);
        }
        int buf = c & 1;

        // dt compute phase: 4 values per thread
        {
            int j  = tid & 63;
            int cb = (tid >> 6) << 2;
            float a0 = sbias[cb + 0], a1 = sbias[cb + 1];
            float a2 = sbias[cb + 2], a3 = sbias[cb + 3];
#pragma unroll
            for (int k = 0; k < 16; k++) {
                float dv = sdtr[buf][j][k];
                a0 = fmaf(dv, swdt[k][cb + 0], a0);
                a1 = fmaf(dv, swdt[k][cb + 1], a1);
                a2 = fmaf(dv, swdt[k][cb + 2], a2);
                a3 = fmaf(dv, swdt[k][cb + 3], a3);
            }
            sdtv[j][cb + 0] = (a0 > 20.f) ? a0 : log1pf(__expf(a0));
            sdtv[j][cb + 1] = (a1 > 20.f) ? a1 : log1pf(__expf(a1));
            sdtv[j][cb + 2] = (a2 > 20.f) ? a2 : log1pf(__expf(a2));
            sdtv[j][cb + 3] = (a3 > 20.f) ? a3 : log1pf(__expf(a3));
        }
        __syncthreads();

#pragma unroll 4
        for (int j = 0; j < 64; j++) {
            float dtv = sdtv[j][wch];
            float xv  = sxm[buf][j][wch];
            float Bv  = sB[buf][j][s];
            float Cv  = sC[buf][j][s];
            float dA  = __expf(dtv * a);
            h = fmaf(dA, h, dtv * xv * Bv);
            float p = h * Cv;
            p += __shfl_xor_sync(0xffffffffu, p, 8);
            p += __shfl_xor_sync(0xffffffffu, p, 4);
            p += __shfl_xor_sync(0xffffffffu, p, 2);
            p += __shfl_xor_sync(0xffffffffu, p, 1);
            if (s == 0) sy[j][wch] = p;
        }
        __syncthreads();

        // gated flush
        {
            float4 pv = *(float4*)&sy[j4][i4];
            float4 xv = *(float4*)&sxm[buf][j4][i4];
            float4 zv = *(float4*)&sz[buf][j4][i4];
            float o0 = fmaf(xv.x, Dv.x, pv.x) * (zv.x / (1.0f + __expf(-zv.x)));
            float o1 = fmaf(xv.y, Dv.y, pv.y) * (zv.y / (1.0f + __expf(-zv.y)));
            float o2 = fmaf(xv.z, Dv.z, pv.z) * (zv.z / (1.0f + __expf(-zv.z)));
            float o3 = fmaf(xv.w, Dv.w, pv.w) * (zv.w / (1.0f + __expf(-zv.w)));
            uint2 packed;
            packed.x = pkbf16(o0, o1);
            packed.y = pkbf16(o2, o3);
            size_t t = (size_t)(tb + c * 64 + j4);
            *(uint2*)(yg + t * DIN + d0 + i4) = packed;
        }
        if (more) {
            int nb = buf ^ 1;
            sdtr[nb][j4][i4 + 0] = rd.x; sdtr[nb][j4][i4 + 1] = rd.y;
            sdtr[nb][j4][i4 + 2] = rd.z; sdtr[nb][j4][i4 + 3] = rd.w;
            float2 xlo = __bfloat1622float2(*(__nv_bfloat162*)&rxm.x);
            float2 xhi = __bfloat1622float2(*(__nv_bfloat162*)&rxm.y);
            sxm[nb][j4][i4 + 0] = xlo.x; sxm[nb][j4][i4 + 1] = xlo.y;
            sxm[nb][j4][i4 + 2] = xhi.x; sxm[nb][j4][i4 + 3] = xhi.y;
            *(float4*)&sB[nb][j4][i4] = rb;
            *(float4*)&sC[nb][j4][i4] = rc;
            *(float4*)&sz[nb][j4][i4] = rz;
        }
        __syncthreads();
    }
}

// ---------------------------- launch ---------------------------------------
extern "C" void kernel_launch(void* const* d_in, const int* in_sizes, int n_in,
                              void* d_out, int out_size) {
    const float* x      = (const float*)d_in[0];
    const float* ln1_g  = (const float*)d_in[1];
    const float* ln1_b  = (const float*)d_in[2];
    const float* ln2_g  = (const float*)d_in[3];
    const float* ln2_b  = (const float*)d_in[4];
    const float* W_in   = (const float*)d_in[5];
    const float* conv_w = (const float*)d_in[6];
    const float* conv_b = (const float*)d_in[7];
    const float* W_x    = (const float*)d_in[8];
    const float* W_dt   = (const float*)d_in[9];
    const float* b_dt   = (const float*)d_in[10];
    const float* A_log  = (const float*)d_in[11];
    const float* D_par  = (const float*)d_in[12];
    const float* W_out  = (const float*)d_in[13];
    const float* W1     = (const float*)d_in[14];
    const float* b1     = (const float*)d_in[15];
    const float* W2     = (const float*)d_in[16];
    const float* b2     = (const float*)d_in[17];
    float* out = (float*)d_out;

    float *xt, *xz, *dbl, *wxp, *x2, *x3;
    __nv_bfloat16 *xn, *xm, *yg, *xn2, *h1;
    cudaGetSymbolAddress((void**)&xt,  g_xt);
    cudaGetSymbolAddress((void**)&xn,  g_xn);
    cudaGetSymbolAddress((void**)&xz,  g_xz);
    cudaGetSymbolAddress((void**)&xm,  g_xm);
    cudaGetSymbolAddress((void**)&dbl, g_dbl);
    cudaGetSymbolAddress((void**)&wxp, g_wxp);
    cudaGetSymbolAddress((void**)&yg,  g_yg);
    cudaGetSymbolAddress((void**)&x2,  g_x2);
    cudaGetSymbolAddress((void**)&xn2, g_xn2);
    cudaGetSymbolAddress((void**)&h1,  g_h1);
    cudaGetSymbolAddress((void**)&x3,  g_x3);

    // 0) pad W_x (independent)
    pad_wx_k<<<(DIN * DBLS) / 256, 256>>>(W_x, wxp);
    // 1) fused transpose + LN1 (xn -> bf16)
    trln_k<<<dim3(LL / 32, BB), dim3(32, 8)>>>(x, xt, xn, ln1_g, ln1_b);
    // 2) xz = xn @ W_in  (A bf16, out f32)
    bf16gemm_k<0, 1, 0><<<dim3((2 * DIN) / 128, MM / 128), 256>>>(xn, W_in, xz, MM, 2 * DIN, CC, nullptr, nullptr);
    // 3) depthwise causal conv + silu (xm -> bf16)
    conv_silu_k<<<(MM * DIN / 4) / 256, 256>>>(xz, conv_w, conv_b, xm);
    // 4) dbl = xm @ W_x (A bf16, out f32)
    bf16gemm_k<0, 1, 0><<<dim3(DBLS / 128, MM / 128), 256>>>(xm, wxp, dbl, MM, DBLS, DIN, nullptr, nullptr);
    // 5) selective scan v3 (fused dt + gate; yg -> bf16)
    scan3_k<<<dim3(DIN / 16, BB), 256>>>(xm, dbl, A_log, xz, D_par, W_dt, b_dt, yg);
    // 6) x2 = yg @ W_out + res  (A bf16, out f32)
    bf16gemm_k<1, 1, 0><<<dim3(CC / 128, MM / 128), 256>>>(yg, W_out, x2, MM, CC, DIN, nullptr, xt);
    // 7) LN2 (xn2 -> bf16)
    layernorm_k<<<MM, 256>>>(x2, xn2, ln2_g, ln2_b);
    // 8) h1 = gelu(xn2 @ W1 + b1)  (A bf16, out bf16)
    bf16gemm_k<2, 1, 1><<<dim3(HID / 128, MM / 128), 256>>>(xn2, W1, h1, MM, HID, CC, b1, nullptr);
    // 9) x3 = h1 @ W2 + b2 + x2  (A bf16, out f32)
    bf16gemm_k<3, 1, 0><<<dim3(CC / 128, MM / 128), 256>>>(h1, W2, x3, MM, CC, HID, b2, x2);
    // 10) transpose back (B,L,C) -> (B,C,L)
    transpose_k<<<dim3(CC / 32, LL / 32, BB), dim3(32, 8)>>>(x3, out, LL, CC);
}